// round 8
// baseline (speedup 1.0000x reference)
#include <cuda_runtime.h>

// WavUnPacking: inverse Haar DWT (db1, per-2x2 butterfly + interleave).
// x: (B=8, C=256, H=128, W=128) fp32 -> out: (B=8, C4=64, 2H=256, 2W=256) fp32
//
// R8 (final hint-matrix cell): R4's dense mapping — thread-per-output-f4-column,
// 4 dense LDG.64 reads, 2 dense STG.128 writes — with default-cached loads and
// default write-back stores (no .cs), block=256.
// Converged state: all coalescing is full-line; DRAM ~75% = practical HBM
// ceiling for this 50/50 R/W multi-stream pattern (MLP/persistence/hints all
// measured neutral in R5/R6/R7).

static constexpr int B  = 8;
static constexpr int C4 = 64;   // output channels
static constexpr int H  = 128;
static constexpr int J  = 64;   // output float4 columns per row

__global__ void __launch_bounds__(256)
wav_unpack_kernel(const float2* __restrict__ x, float4* __restrict__ out)
{
    int idx = blockIdx.x * blockDim.x + threadIdx.x;
    // idx layout: [bc (512)][h (128)][j (64)]
    int j  = idx & (J - 1);           // output f4 column
    int h  = (idx >> 6) & (H - 1);
    int bc = idx >> 13;               // 0..511
    int b  = bc >> 6;
    int c  = bc & (C4 - 1);

    // input as float2: per-channel plane = 128 rows * 64 float2
    const int plane2 = H * 64;
    int base = ((b * 256 + c) * H + h) * 64 + j;   // float2 index of w=2j
    const int cs = C4 * plane2;                    // subband stride (float2)

    // 4 independent dense loads (default caching)
    float2 ll = __ldg(&x[base]);
    float2 lh = __ldg(&x[base + cs]);
    float2 hl = __ldg(&x[base + 2 * cs]);
    float2 hh = __ldg(&x[base + 3 * cs]);

    float4 top, bot;
    {
        float a, bb, cc, d;
        a = ll.x; bb = lh.x; cc = hl.x; d = hh.x;
        top.x = 0.5f*(a+bb+cc+d);  top.y = 0.5f*(a+bb-cc-d);
        bot.x = 0.5f*(a-bb+cc-d);  bot.y = 0.5f*(a-bb-cc+d);
        a = ll.y; bb = lh.y; cc = hl.y; d = hh.y;
        top.z = 0.5f*(a+bb+cc+d);  top.w = 0.5f*(a+bb-cc-d);
        bot.z = 0.5f*(a-bb+cc-d);  bot.w = 0.5f*(a-bb-cc+d);
    }

    // output: 256 rows * 64 float4/row per (b,c) plane; rows 2h, 2h+1
    int otop = (bc * 256 + 2 * h) * 64 + j;
    out[otop]      = top;   // dense across warp: lane j -> f4 column j
    out[otop + 64] = bot;
}

extern "C" void kernel_launch(void* const* d_in, const int* in_sizes, int n_in,
                              void* d_out, int out_size)
{
    const float2* x = (const float2*)d_in[0];
    float4* out = (float4*)d_out;

    int total_threads = B * C4 * H * J;  // 4,194,304
    int block = 256;
    int grid = total_threads / block;    // 16384
    wav_unpack_kernel<<<grid, block>>>(x, out);
}

// round 9
// speedup vs baseline: 1.0059x; 1.0059x over previous
#include <cuda_runtime.h>

// WavUnPacking: inverse Haar DWT (db1, per-2x2 butterfly + interleave).
// x: (B=8, C=256, H=128, W=128) fp32 -> out: (B=8, C4=64, 2H=256, 2W=256) fp32
//
// FINAL (= R7, best measured 43.5us): thread-per-output-f4-column mapping.
//  - 4 dense LDG.64 reads (one float2 per subband; 256B/warp-instr, full lines)
//  - 2 dense STG.128 writes (512B/warp-instr, full lines; lane j -> f4 col j)
//  - __ldg loads, __stcs stores, block=512, 24 regs, occ ~74-79%.
// Converged at DRAM ~75% (5.9-6.0 TB/s) — measured invariant across MLP depth
// (R5), persistent grid (R6), block size (R3/R7), and the full load/store
// cache-hint matrix (R3/R4/R7/R8). Remaining gap to spec is HBM R/W-mix
// turnaround efficiency, not SM-schedulable.

static constexpr int B  = 8;
static constexpr int C4 = 64;   // output channels
static constexpr int H  = 128;
static constexpr int J  = 64;   // output float4 columns per row

__global__ void __launch_bounds__(512)
wav_unpack_kernel(const float2* __restrict__ x, float4* __restrict__ out)
{
    int idx = blockIdx.x * blockDim.x + threadIdx.x;
    // idx layout: [bc (512)][h (128)][j (64)]
    int j  = idx & (J - 1);           // output f4 column
    int h  = (idx >> 6) & (H - 1);
    int bc = idx >> 13;               // 0..511
    int b  = bc >> 6;
    int c  = bc & (C4 - 1);

    // input as float2: per-channel plane = 128 rows * 64 float2
    const int plane2 = H * 64;
    int base = ((b * 256 + c) * H + h) * 64 + j;   // float2 index of w=2j
    const int cs = C4 * plane2;                    // subband stride (float2)

    // 4 independent dense loads
    float2 ll = __ldg(&x[base]);
    float2 lh = __ldg(&x[base + cs]);
    float2 hl = __ldg(&x[base + 2 * cs]);
    float2 hh = __ldg(&x[base + 3 * cs]);

    float4 top, bot;
    {
        float a, bb, cc, d;
        a = ll.x; bb = lh.x; cc = hl.x; d = hh.x;
        top.x = 0.5f*(a+bb+cc+d);  top.y = 0.5f*(a+bb-cc-d);
        bot.x = 0.5f*(a-bb+cc-d);  bot.y = 0.5f*(a-bb-cc+d);
        a = ll.y; bb = lh.y; cc = hl.y; d = hh.y;
        top.z = 0.5f*(a+bb+cc+d);  top.w = 0.5f*(a+bb-cc-d);
        bot.z = 0.5f*(a-bb+cc-d);  bot.w = 0.5f*(a-bb-cc+d);
    }

    // output: 256 rows * 64 float4/row per (b,c) plane; rows 2h, 2h+1
    int otop = (bc * 256 + 2 * h) * 64 + j;
    __stcs(&out[otop],      top);   // dense across warp: lane j -> f4 column j
    __stcs(&out[otop + 64], bot);
}

extern "C" void kernel_launch(void* const* d_in, const int* in_sizes, int n_in,
                              void* d_out, int out_size)
{
    const float2* x = (const float2*)d_in[0];
    float4* out = (float4*)d_out;

    int total_threads = B * C4 * H * J;  // 4,194,304
    int block = 512;
    int grid = total_threads / block;    // 8192
    wav_unpack_kernel<<<grid, block>>>(x, out);
}